// round 4
// baseline (speedup 1.0000x reference)
#include <cuda_runtime.h>

#define NBATCH 8192
#define NLAT   16
#define TPB    512

// dynamic shared memory layout (bytes)
#define O_W2 0          // 128*128 f32 = 65536
#define O_HT 65536      // 128*128 f32 = 65536  (H1 transposed [j][p])
#define O_W3 131072     // 128*32 f32  = 16384
#define O_WP 147456     // 32*128 f32  = 16384  (fspool weights)
#define O_X  163840     // 2048
#define O_W1 165888     // 2048
#define O_B1 167936     // 512
#define O_B2 168448     // 512
#define O_B3 168960     // 128
#define O_PL 169088     // 128
#define SMEM_BYTES 169216
// aliases over dead W2 region (valid after layer2 reads + syncthreads):
#define O_KEY 0         // u32[32*132] = 16896
#define O_ZC  16896     // f32[32*132] = 16896

typedef unsigned long long ull;

__device__ __forceinline__ ull pk2(float lo, float hi) {
    ull r; asm("mov.b64 %0, {%1,%2};" : "=l"(r) : "f"(lo), "f"(hi)); return r;
}
__device__ __forceinline__ float2 upk2(ull v) {
    float2 r; asm("mov.b64 {%0,%1}, %2;" : "=f"(r.x), "=f"(r.y) : "l"(v)); return r;
}
#define FMA2(d,a,b,c) asm("fma.rn.f32x2 %0, %1, %2, %3;" : "=l"(d) : "l"(a), "l"(b), "l"(c))
#define ADD2(d,a,b)   asm("add.rn.f32x2 %0, %1, %2;"     : "=l"(d) : "l"(a), "l"(b))

__global__ __launch_bounds__(TPB, 1)
void enc_kernel(const float* __restrict__ x,  const float* __restrict__ W1,
                const float* __restrict__ b1, const float* __restrict__ W2,
                const float* __restrict__ b2, const float* __restrict__ W3,
                const float* __restrict__ b3, const float* __restrict__ pwm,
                const float* __restrict__ eps, float* __restrict__ out)
{
    extern __shared__ __align__(16) char smem[];
    const int tid = threadIdx.x;
    const int b = blockIdx.x;

    // ------------------- stage to shared -------------------
    {
        const float4* g4 = (const float4*)W2;
        float4* s4 = (float4*)(smem + O_W2);
        #pragma unroll
        for (int i = 0; i < 8; i++) s4[tid + i*TPB] = g4[tid + i*TPB];
        g4 = (const float4*)W3; s4 = (float4*)(smem + O_W3);
        #pragma unroll
        for (int i = 0; i < 2; i++) s4[tid + i*TPB] = g4[tid + i*TPB];
        if (tid < 128) {
            ((float4*)(smem + O_W1))[tid] = ((const float4*)W1)[tid];
            ((float4*)(smem + O_X ))[tid] = ((const float4*)(x + (size_t)b * 512))[tid];
        }
        if (tid >= 128 && tid < 160) ((float4*)(smem + O_B1))[tid-128] = ((const float4*)b1)[tid-128];
        if (tid >= 160 && tid < 192) ((float4*)(smem + O_B2))[tid-160] = ((const float4*)b2)[tid-160];
        if (tid >= 192 && tid < 200) ((float4*)(smem + O_B3))[tid-192] = ((const float4*)b3)[tid-192];
        float* sWp = (float*)(smem + O_WP);
        for (int i = tid; i < 4096; i += TPB) {
            int c = i >> 7, pp = i & 127;
            float pos = (float)pp / 127.0f * 20.0f;
            int idx = (int)pos; if (idx > 20) idx = 20;
            float frac = pos - (float)idx;
            int idx2 = idx + 1; if (idx2 > 20) idx2 = 20;
            sWp[i] = (1.0f - frac) * pwm[c*21 + idx] + frac * pwm[c*21 + idx2];
        }
    }
    __syncthreads();

    // ------------------- layer 1 (store transposed [j][p]) -------------------
    {
        float* sHt = (float*)(smem + O_HT);
        const float* sW1 = (const float*)(smem + O_W1);
        const float* sX  = (const float*)(smem + O_X);
        const float* sb1 = (const float*)(smem + O_B1);
        const int p = tid & 127, quad = tid >> 7;   // quad in 0..3
        float x0 = sX[p*4+0], x1 = sX[p*4+1], x2 = sX[p*4+2], x3 = sX[p*4+3];
        const int j0 = quad * 32;
        #pragma unroll 8
        for (int j = j0; j < j0 + 32; j++) {
            float a = sb1[j];
            a = fmaf(x0, sW1[j],       a);
            a = fmaf(x1, sW1[128 + j], a);
            a = fmaf(x2, sW1[256 + j], a);
            a = fmaf(x3, sW1[384 + j], a);
            sHt[j*128 + p] = fmaxf(a, 0.0f);
        }
    }
    __syncthreads();

    // ------------------- layer 2: thread tile = 2 points x 16 k -------------------
    const int kg = tid & 7;          // 8 k-groups of 16
    const int pg = tid >> 3;         // 64 p-groups of 2
    const int p0 = pg * 2;
    const int k0 = kg * 16;

    ull acc[2][8];
    {
        const float* sb2 = (const float*)(smem + O_B2);
        #pragma unroll
        for (int q = 0; q < 8; q++) {
            ull bi = pk2(sb2[k0 + 2*q], sb2[k0 + 2*q + 1]);
            acc[0][q] = bi; acc[1][q] = bi;
        }
        const float* hp = (const float*)(smem + O_HT) + p0;
        const float* wp = (const float*)(smem + O_W2) + k0;
        #pragma unroll 4
        for (int j = 0; j < 128; j++) {
            float2 h2 = *(const float2*)hp; hp += 128;
            ull ha = pk2(h2.x, h2.x), hb = pk2(h2.y, h2.y);
            ulonglong2 w0 = *(const ulonglong2*)(wp);
            ulonglong2 w1 = *(const ulonglong2*)(wp + 4);
            ulonglong2 w2v = *(const ulonglong2*)(wp + 8);
            ulonglong2 w3v = *(const ulonglong2*)(wp + 12); wp += 128;
            ull w[8] = {w0.x, w0.y, w1.x, w1.y, w2v.x, w2v.y, w3v.x, w3v.y};
            #pragma unroll
            for (int q = 0; q < 8; q++) {
                FMA2(acc[0][q], ha, w[q], acc[0][q]);
                FMA2(acc[1][q], hb, w[q], acc[1][q]);
            }
        }
    }

    // relu -> hv[pp][k] (16 local k's per thread)
    float hv[2][16];
    #pragma unroll
    for (int pp = 0; pp < 2; pp++)
        #pragma unroll
        for (int q = 0; q < 8; q++) {
            float2 t = upk2(acc[pp][q]);
            hv[pp][2*q]   = fmaxf(t.x, 0.0f);
            hv[pp][2*q+1] = fmaxf(t.y, 0.0f);
        }
    __syncthreads();   // all reads of W2/Ht done -> W2 region reusable

    // ------------------- layer 3 in registers, 2 chunks of 16 channels ----------
    {
        const float* sW3f = (const float*)(smem + O_W3);
        const float* sb3  = (const float*)(smem + O_B3);
        unsigned* sKey = (unsigned*)(smem + O_KEY);
        float* sZc = (float*)(smem + O_ZC);
        #pragma unroll
        for (int ch = 0; ch < 2; ch++) {
            const int c0 = ch * 16;
            ull zc[2][8];
            #pragma unroll
            for (int q = 0; q < 8; q++) {
                ull bi = (kg == 0) ? pk2(sb3[c0+2*q], sb3[c0+2*q+1]) : 0ull;
                zc[0][q] = bi; zc[1][q] = bi;
            }
            const float* w3p = sW3f + (size_t)k0 * 32 + c0;
            #pragma unroll 4
            for (int k = 0; k < 16; k++) {
                ulonglong2 wa = *(const ulonglong2*)(w3p);
                ulonglong2 wb = *(const ulonglong2*)(w3p + 4);
                ulonglong2 wcv = *(const ulonglong2*)(w3p + 8);
                ulonglong2 wd = *(const ulonglong2*)(w3p + 12); w3p += 32;
                ull w[8] = {wa.x, wa.y, wb.x, wb.y, wcv.x, wcv.y, wd.x, wd.y};
                ull h0 = pk2(hv[0][k], hv[0][k]);
                ull h1 = pk2(hv[1][k], hv[1][k]);
                #pragma unroll
                for (int q = 0; q < 8; q++) {
                    FMA2(zc[0][q], h0, w[q], zc[0][q]);
                    FMA2(zc[1][q], h1, w[q], zc[1][q]);
                }
            }
            // butterfly-reduce across the 8 kgroup lanes (same pg within warp)
            #pragma unroll
            for (int s = 1; s <= 4; s <<= 1)
                #pragma unroll
                for (int pp = 0; pp < 2; pp++)
                    #pragma unroll
                    for (int q = 0; q < 8; q++) {
                        ull o = __shfl_xor_sync(0xffffffffu, zc[pp][q], s);
                        ADD2(zc[pp][q], zc[pp][q], o);
                    }
            // lane kg keeps channel pair q=kg of this chunk
            const int c = c0 + 2*kg;
            #pragma unroll
            for (int pp = 0; pp < 2; pp++) {
                float2 t = upk2(zc[pp][kg]);
                int pw_ = p0 + pp;
                {
                    float zv = t.x;
                    sZc[c*132 + pw_] = zv;
                    unsigned u = __float_as_uint(zv);
                    unsigned s2 = (u & 0x80000000u) ? ~u : (u | 0x80000000u);
                    sKey[c*132 + pw_] = (s2 & 0xFFFFFF80u) | (unsigned)(127 - pw_);
                }
                {
                    float zv = t.y;
                    sZc[(c+1)*132 + pw_] = zv;
                    unsigned u = __float_as_uint(zv);
                    unsigned s2 = (u & 0x80000000u) ? ~u : (u | 0x80000000u);
                    sKey[(c+1)*132 + pw_] = (s2 & 0xFFFFFF80u) | (unsigned)(127 - pw_);
                }
            }
        }
    }
    __syncthreads();

    // ------------------- ranking + weighted pool (2 channels per warp) ----------
    {
        const unsigned* sKey = (const unsigned*)(smem + O_KEY);
        const float* sZc = (const float*)(smem + O_ZC);
        const float* sWp = (const float*)(smem + O_WP);
        float* sPl = (float*)(smem + O_PL);
        const int w = tid >> 5, lane = tid & 31;
        #pragma unroll
        for (int cc = 0; cc < 2; cc++) {
            const int c = w * 2 + cc;
            const unsigned* kp = sKey + c * 132;
            const float* zp = sZc + c * 132;
            unsigned k0_ = kp[lane], k1 = kp[lane+32], k2 = kp[lane+64], k3 = kp[lane+96];
            int r0 = 0, r1 = 0, r2 = 0, r3 = 0;
            const uint4* kq4 = (const uint4*)kp;
            #pragma unroll 8
            for (int qq = 0; qq < 32; qq++) {
                uint4 kq = kq4[qq];
                r0 += (kq.x > k0_) + (kq.y > k0_) + (kq.z > k0_) + (kq.w > k0_);
                r1 += (kq.x > k1)  + (kq.y > k1)  + (kq.z > k1)  + (kq.w > k1);
                r2 += (kq.x > k2)  + (kq.y > k2)  + (kq.z > k2)  + (kq.w > k2);
                r3 += (kq.x > k3)  + (kq.y > k3)  + (kq.z > k3)  + (kq.w > k3);
            }
            const float* wc = sWp + c * 128;
            float sum = zp[lane]    * wc[r0]
                      + zp[lane+32] * wc[r1]
                      + zp[lane+64] * wc[r2]
                      + zp[lane+96] * wc[r3];
            #pragma unroll
            for (int ofs = 16; ofs > 0; ofs >>= 1)
                sum += __shfl_xor_sync(0xffffffffu, sum, ofs);
            if (lane == 0) sPl[c] = sum;
        }
    }
    __syncthreads();

    // ------------------- reparameterize + write -------------------
    if (tid < 16) {
        const float* sPl = (const float*)(smem + O_PL);
        float mu = sPl[2*tid];
        float lv = sPl[2*tid + 1];
        float e  = eps[(size_t)b*16 + tid];
        float smp = fmaf(e, expf(0.5f * lv), mu);
        out[(size_t)b*16 + tid] = mu;
        out[(size_t)(NBATCH*NLAT)   + (size_t)b*16 + tid] = lv;
        out[(size_t)(2*NBATCH*NLAT) + (size_t)b*16 + tid] = smp;
    }
}

extern "C" void kernel_launch(void* const* d_in, const int* in_sizes, int n_in,
                              void* d_out, int out_size) {
    const float* x   = (const float*)d_in[0];
    const float* W1  = (const float*)d_in[1];
    const float* b1  = (const float*)d_in[2];
    const float* W2  = (const float*)d_in[3];
    const float* b2  = (const float*)d_in[4];
    const float* W3  = (const float*)d_in[5];
    const float* b3  = (const float*)d_in[6];
    const float* pwm = (const float*)d_in[7];
    const float* eps = (const float*)d_in[8];
    float* out = (float*)d_out;

    cudaFuncSetAttribute(enc_kernel, cudaFuncAttributeMaxDynamicSharedMemorySize, SMEM_BYTES);
    enc_kernel<<<NBATCH, TPB, SMEM_BYTES>>>(x, W1, b1, W2, b2, W3, b3, pwm, eps, out);
}

// round 5
// speedup vs baseline: 2.7475x; 2.7475x over previous
#include <cuda_runtime.h>

#define NBATCH 8192
#define NLAT   16
#define TPB    512

// dynamic shared memory layout (bytes)
#define O_W2  0          // 128*128 f32 = 65536
#define O_HT  65536      // 128*128 f32 = 65536  (H1 transposed [j][p])
#define O_W3T 131072     // 32*132 f32  = 16896  (W3 transposed [c][k], padded)
#define O_WP  147968     // 32*128 f32  = 16384  (fspool weights)
#define O_X   164352     // 2048
#define O_W1  166400     // 2048
#define O_B1  168448     // 512
#define O_B2  168960     // 512
#define O_B3  169472     // 128
#define O_PL  169600     // 128
#define SMEM_BYTES 169728
// aliases over dead W2 region (valid after layer2 reads + syncthreads):
#define O_KEY 0          // u32[32*132] = 16896
#define O_ZC  16896      // f32[32*132] = 16896

typedef unsigned long long ull;

__device__ __forceinline__ ull pk2(float lo, float hi) {
    ull r; asm("mov.b64 %0, {%1,%2};" : "=l"(r) : "f"(lo), "f"(hi)); return r;
}
__device__ __forceinline__ float2 upk2(ull v) {
    float2 r; asm("mov.b64 {%0,%1}, %2;" : "=f"(r.x), "=f"(r.y) : "l"(v)); return r;
}
#define FMA2(d,a,b,c) asm("fma.rn.f32x2 %0, %1, %2, %3;" : "=l"(d) : "l"(a), "l"(b), "l"(c))
#define ADD2(d,a,b)   asm("add.rn.f32x2 %0, %1, %2;"     : "=l"(d) : "l"(a), "l"(b))

__global__ __launch_bounds__(TPB, 1)
void enc_kernel(const float* __restrict__ x,  const float* __restrict__ W1,
                const float* __restrict__ b1, const float* __restrict__ W2,
                const float* __restrict__ b2, const float* __restrict__ W3,
                const float* __restrict__ b3, const float* __restrict__ pwm,
                const float* __restrict__ eps, float* __restrict__ out)
{
    extern __shared__ __align__(16) char smem[];
    const int tid = threadIdx.x;
    const int b = blockIdx.x;

    // ------------------- stage to shared -------------------
    {
        const float4* g4 = (const float4*)W2;
        float4* s4 = (float4*)(smem + O_W2);
        #pragma unroll
        for (int i = 0; i < 8; i++) s4[tid + i*TPB] = g4[tid + i*TPB];
        // W3 transposed: sW3T[c*132 + k] = W3[k*32 + c]
        float* sW3T = (float*)(smem + O_W3T);
        #pragma unroll
        for (int r = 0; r < 8; r++) {
            int i = tid + r*TPB;               // 4096 elements
            float v = W3[i];
            sW3T[(i & 31) * 132 + (i >> 5)] = v;
        }
        if (tid < 128) {
            ((float4*)(smem + O_W1))[tid] = ((const float4*)W1)[tid];
            ((float4*)(smem + O_X ))[tid] = ((const float4*)(x + (size_t)b * 512))[tid];
        }
        if (tid >= 128 && tid < 160) ((float4*)(smem + O_B1))[tid-128] = ((const float4*)b1)[tid-128];
        if (tid >= 160 && tid < 192) ((float4*)(smem + O_B2))[tid-160] = ((const float4*)b2)[tid-160];
        if (tid >= 192 && tid < 200) ((float4*)(smem + O_B3))[tid-192] = ((const float4*)b3)[tid-192];
        float* sWp = (float*)(smem + O_WP);
        for (int i = tid; i < 4096; i += TPB) {
            int c = i >> 7, pp = i & 127;
            float pos = (float)pp / 127.0f * 20.0f;
            int idx = (int)pos; if (idx > 20) idx = 20;
            float frac = pos - (float)idx;
            int idx2 = idx + 1; if (idx2 > 20) idx2 = 20;
            sWp[i] = (1.0f - frac) * pwm[c*21 + idx] + frac * pwm[c*21 + idx2];
        }
    }
    __syncthreads();

    // ------------------- layer 1 (store transposed [j][p]) -------------------
    {
        float* sHt = (float*)(smem + O_HT);
        const float* sW1 = (const float*)(smem + O_W1);
        const float* sX  = (const float*)(smem + O_X);
        const float* sb1 = (const float*)(smem + O_B1);
        const int p = tid & 127, quad = tid >> 7;
        float x0 = sX[p*4+0], x1 = sX[p*4+1], x2 = sX[p*4+2], x3 = sX[p*4+3];
        const int j0 = quad * 32;
        #pragma unroll 8
        for (int j = j0; j < j0 + 32; j++) {
            float a = sb1[j];
            a = fmaf(x0, sW1[j],       a);
            a = fmaf(x1, sW1[128 + j], a);
            a = fmaf(x2, sW1[256 + j], a);
            a = fmaf(x3, sW1[384 + j], a);
            sHt[j*128 + p] = fmaxf(a, 0.0f);
        }
    }
    __syncthreads();

    // ------ layer 2: thread tile = 2 points x 16 k (k = chunks {kg,kg+8,kg+16,kg+24}) ------
    const int kg = tid & 7;          // 8 k-groups
    const int pg = tid >> 3;         // 64 p-groups of 2
    const int p0 = pg * 2;

    ull acc[2][8];                   // acc[pp][2i+u] = k-chunk (8i+kg), float pair u
    {
        const float4* sb24 = (const float4*)(smem + O_B2);
        #pragma unroll
        for (int i = 0; i < 4; i++) {
            float4 bb = sb24[8*i + kg];
            acc[0][2*i]   = pk2(bb.x, bb.y);  acc[0][2*i+1] = pk2(bb.z, bb.w);
            acc[1][2*i]   = acc[0][2*i];      acc[1][2*i+1] = acc[0][2*i+1];
        }
        const float* hp = (const float*)(smem + O_HT) + p0;
        const ulonglong2* wr = (const ulonglong2*)(smem + O_W2) + kg;  // +16B*kg
        #pragma unroll 4
        for (int j = 0; j < 128; j++) {
            float2 h2 = *(const float2*)hp; hp += 128;
            ull ha = pk2(h2.x, h2.x), hb = pk2(h2.y, h2.y);
            #pragma unroll
            for (int i = 0; i < 4; i++) {
                ulonglong2 w = wr[8*i];      // chunk 8i+kg of this row: contiguous across warp
                FMA2(acc[0][2*i],   ha, w.x, acc[0][2*i]);
                FMA2(acc[0][2*i+1], ha, w.y, acc[0][2*i+1]);
                FMA2(acc[1][2*i],   hb, w.x, acc[1][2*i]);
                FMA2(acc[1][2*i+1], hb, w.y, acc[1][2*i+1]);
            }
            wr += 32;                        // next 128-float row
        }
    }

    // relu -> packed (point0,point1) per local k: hp2[i*4+t]
    ull hp2[16];
    #pragma unroll
    for (int i = 0; i < 4; i++) {
        #pragma unroll
        for (int u = 0; u < 2; u++) {
            float2 t0 = upk2(acc[0][2*i+u]);
            float2 t1 = upk2(acc[1][2*i+u]);
            hp2[i*4 + 2*u]     = pk2(fmaxf(t0.x, 0.f), fmaxf(t1.x, 0.f));
            hp2[i*4 + 2*u + 1] = pk2(fmaxf(t0.y, 0.f), fmaxf(t1.y, 0.f));
        }
    }
    __syncthreads();   // all reads of W2/Ht done -> W2 region reusable

    // ------------------- layer 3: 2 chunks of 16 channels, conflict-free W3T ----------
    {
        const float* sW3T = (const float*)(smem + O_W3T);
        const float* sb3  = (const float*)(smem + O_B3);
        unsigned* sKey = (unsigned*)(smem + O_KEY);
        float* sZc = (float*)(smem + O_ZC);
        #pragma unroll
        for (int ch = 0; ch < 2; ch++) {
            const int c0 = ch * 16;
            ull z2[16];
            #pragma unroll
            for (int m = 0; m < 16; m++) {
                float bv = sb3[c0 + m];
                z2[m] = (kg == 0) ? pk2(bv, bv) : 0ull;
            }
            #pragma unroll
            for (int m = 0; m < 16; m++) {
                const float4* w4 = (const float4*)(sW3T + (c0 + m) * 132) + kg;
                #pragma unroll
                for (int i = 0; i < 4; i++) {
                    float4 w = w4[8*i];      // chunk 8i+kg: contiguous across warp
                    ull w0 = pk2(w.x, w.x), w1 = pk2(w.y, w.y);
                    ull w2v = pk2(w.z, w.z), w3v = pk2(w.w, w.w);
                    FMA2(z2[m], hp2[i*4+0], w0,  z2[m]);
                    FMA2(z2[m], hp2[i*4+1], w1,  z2[m]);
                    FMA2(z2[m], hp2[i*4+2], w2v, z2[m]);
                    FMA2(z2[m], hp2[i*4+3], w3v, z2[m]);
                }
            }
            // butterfly-reduce across the 8 kg lanes
            #pragma unroll
            for (int s = 1; s <= 4; s <<= 1)
                #pragma unroll
                for (int m = 0; m < 16; m++) {
                    ull o = __shfl_xor_sync(0xffffffffu, z2[m], s);
                    ADD2(z2[m], z2[m], o);
                }
            // lane kg writes channels c0+2kg, c0+2kg+1 (both points)
            #pragma unroll
            for (int u = 0; u < 2; u++) {
                const int c = c0 + 2*kg + u;
                float2 t = upk2(z2[2*kg + u]);
                float zv0 = t.x, zv1 = t.y;
                sZc[c*132 + p0]     = zv0;
                sZc[c*132 + p0 + 1] = zv1;
                unsigned u0 = __float_as_uint(zv0);
                unsigned s0 = (u0 & 0x80000000u) ? ~u0 : (u0 | 0x80000000u);
                sKey[c*132 + p0]     = (s0 & 0xFFFFFF80u) | (unsigned)(127 - p0);
                unsigned u1 = __float_as_uint(zv1);
                unsigned s1 = (u1 & 0x80000000u) ? ~u1 : (u1 | 0x80000000u);
                sKey[c*132 + p0 + 1] = (s1 & 0xFFFFFF80u) | (unsigned)(127 - (p0+1));
            }
        }
    }
    __syncthreads();

    // ------------------- ranking + weighted pool (2 channels per warp) ----------
    {
        const unsigned* sKey = (const unsigned*)(smem + O_KEY);
        const float* sZc = (const float*)(smem + O_ZC);
        const float* sWp = (const float*)(smem + O_WP);
        float* sPl = (float*)(smem + O_PL);
        const int w = tid >> 5, lane = tid & 31;
        #pragma unroll
        for (int cc = 0; cc < 2; cc++) {
            const int c = w * 2 + cc;
            const unsigned* kp = sKey + c * 132;
            const float* zp = sZc + c * 132;
            unsigned k0_ = kp[lane], k1 = kp[lane+32], k2 = kp[lane+64], k3 = kp[lane+96];
            int r0 = 0, r1 = 0, r2 = 0, r3 = 0;
            const uint4* kq4 = (const uint4*)kp;
            #pragma unroll 8
            for (int qq = 0; qq < 32; qq++) {
                uint4 kq = kq4[qq];
                r0 += (kq.x > k0_) + (kq.y > k0_) + (kq.z > k0_) + (kq.w > k0_);
                r1 += (kq.x > k1)  + (kq.y > k1)  + (kq.z > k1)  + (kq.w > k1);
                r2 += (kq.x > k2)  + (kq.y > k2)  + (kq.z > k2)  + (kq.w > k2);
                r3 += (kq.x > k3)  + (kq.y > k3)  + (kq.z > k3)  + (kq.w > k3);
            }
            const float* wc = sWp + c * 128;
            float sum = zp[lane]    * wc[r0]
                      + zp[lane+32] * wc[r1]
                      + zp[lane+64] * wc[r2]
                      + zp[lane+96] * wc[r3];
            #pragma unroll
            for (int ofs = 16; ofs > 0; ofs >>= 1)
                sum += __shfl_xor_sync(0xffffffffu, sum, ofs);
            if (lane == 0) sPl[c] = sum;
        }
    }
    __syncthreads();

    // ------------------- reparameterize + write -------------------
    if (tid < 16) {
        const float* sPl = (const float*)(smem + O_PL);
        float mu = sPl[2*tid];
        float lv = sPl[2*tid + 1];
        float e  = eps[(size_t)b*16 + tid];
        float smp = fmaf(e, expf(0.5f * lv), mu);
        out[(size_t)b*16 + tid] = mu;
        out[(size_t)(NBATCH*NLAT)   + (size_t)b*16 + tid] = lv;
        out[(size_t)(2*NBATCH*NLAT) + (size_t)b*16 + tid] = smp;
    }
}

extern "C" void kernel_launch(void* const* d_in, const int* in_sizes, int n_in,
                              void* d_out, int out_size) {
    const float* x   = (const float*)d_in[0];
    const float* W1  = (const float*)d_in[1];
    const float* b1  = (const float*)d_in[2];
    const float* W2  = (const float*)d_in[3];
    const float* b2  = (const float*)d_in[4];
    const float* W3  = (const float*)d_in[5];
    const float* b3  = (const float*)d_in[6];
    const float* pwm = (const float*)d_in[7];
    const float* eps = (const float*)d_in[8];
    float* out = (float*)d_out;

    cudaFuncSetAttribute(enc_kernel, cudaFuncAttributeMaxDynamicSharedMemorySize, SMEM_BYTES);
    enc_kernel<<<NBATCH, TPB, SMEM_BYTES>>>(x, W1, b1, W2, b2, W3, b3, pwm, eps, out);
}